// round 10
// baseline (speedup 1.0000x reference)
#include <cuda_runtime.h>
#include <cstdint>

#define CN0  400000
#define CN1  40000
#define CN2  4000
#define CIN  128
#define CHID 256
#define COUT 64
#define CE1  640000
#define CE2  64000
#define NB1  40
#define NB2  4

// ---- scratch (device globals: no allocation allowed) ----
__device__ float g_h   [CN1 * CHID];
__device__ int   g_cnt1[CN1];
__device__ int   g_off1[CN1 + 1];
__device__ int   g_csr1[CE1];
__device__ int   g_cnt2[CN2];
__device__ int   g_off2[CN2 + 1];
__device__ int   g_csr2[CE2];
__device__ int   g_bsum[64];

// ---------------------------------------------------------------------------
__global__ void k_zero() {
    int i = blockIdx.x * blockDim.x + threadIdx.x;
    if (i < CN1) g_cnt1[i] = 0;
    if (i < CN2) g_cnt2[i] = 0;
}

__global__ void k_count(const int* __restrict__ d1, const int* __restrict__ d2,
                        int E1, int E2) {
    int i = blockIdx.x * blockDim.x + threadIdx.x;
    if (i < E1) atomicAdd(g_cnt1 + d1[i], 1);
    else {
        int j = i - E1;
        if (j < E2) atomicAdd(g_cnt2 + d2[j], 1);
    }
}

// Phase A: per-block exclusive scan, emit block sum (blocks 0..39 L1, 40..43 L2)
__global__ void __launch_bounds__(1024) k_scan_a() {
    int b = blockIdx.x;
    int lay = (b >= NB1);
    int bb = lay ? b - NB1 : b;
    int n = lay ? CN2 : CN1;
    int* cnt = lay ? g_cnt2 : g_cnt1;
    int* off = lay ? g_off2 : g_off1;
    __shared__ int ps[1024];
    int t = threadIdx.x;
    int i = bb * 1024 + t;
    int v = (i < n) ? cnt[i] : 0;
    ps[t] = v;
    __syncthreads();
    #pragma unroll
    for (int d = 1; d < 1024; d <<= 1) {
        int u = (t >= d) ? ps[t - d] : 0;
        __syncthreads();
        ps[t] += u;
        __syncthreads();
    }
    if (i < n) off[i] = ps[t] - v;
    if (t == 1023) g_bsum[b] = ps[1023];
}

// Phase C: compute own block prefix from g_bsum, add it, reset cnt, set off[n]
__global__ void __launch_bounds__(1024) k_scan_c(int E1, int E2) {
    int b = blockIdx.x;
    int lay = (b >= NB1);
    int bb = lay ? b - NB1 : b;
    int n = lay ? CN2 : CN1;
    int segbase = lay ? NB1 : 0;
    int* cnt = lay ? g_cnt2 : g_cnt1;
    int* off = lay ? g_off2 : g_off1;
    __shared__ int add_s;
    int t = threadIdx.x;
    if (t == 0) {
        int s = 0;
        for (int j = segbase; j < b; j++) s += g_bsum[j];
        add_s = s;
    }
    __syncthreads();
    int add = add_s;
    int i = bb * 1024 + t;
    if (i < n) { off[i] += add; cnt[i] = 0; }
    if (i == 0) off[n] = lay ? E2 : E1;
}

__global__ void k_fill(const int* __restrict__ s1, const int* __restrict__ d1,
                       const int* __restrict__ s2, const int* __restrict__ d2,
                       int E1, int E2) {
    int i = blockIdx.x * blockDim.x + threadIdx.x;
    if (i < E1) {
        int d = d1[i];
        int pos = atomicAdd(g_cnt1 + d, 1);
        g_csr1[g_off1[d] + pos] = s1[i];
    } else {
        int j = i - E1;
        if (j < E2) {
            int d = d2[j];
            int pos = atomicAdd(g_cnt2 + d, 1);
            g_csr2[g_off2[d] + pos] = s2[j];
        }
    }
}

// ---------------------------------------------------------------------------
// tf32 helpers
// ---------------------------------------------------------------------------
__device__ __forceinline__ uint32_t f2tf(float v) {
    uint32_t r;
    asm("cvt.rna.tf32.f32 %0, %1;" : "=r"(r) : "f"(v));
    return r;
}

__device__ __forceinline__ void mma_tf32(float* c, const uint32_t* a, const uint32_t* b) {
    asm volatile(
        "mma.sync.aligned.m16n8k8.row.col.f32.tf32.tf32.f32 "
        "{%0,%1,%2,%3}, {%4,%5,%6,%7}, {%8,%9}, {%0,%1,%2,%3};"
        : "+f"(c[0]), "+f"(c[1]), "+f"(c[2]), "+f"(c[3])
        : "r"(a[0]), "r"(a[1]), "r"(a[2]), "r"(a[3]), "r"(b[0]), "r"(b[1]));
}

__device__ __forceinline__ uint32_t s2u(const void* p) {
    return (uint32_t)__cvta_generic_to_shared(p);
}

__device__ __forceinline__ void cp16(uint32_t dst, const void* src) {
    asm volatile("cp.async.cg.shared.global [%0], [%1], 16;"
                 :: "r"(dst), "l"(src));
}

// ---------------------------------------------------------------------------
// FUSED layer-1: gather-mean (CSR) + tf32 GEMM + bias + relu
//   h[m] = relu([mean_{s in N(m)} x_s | x_m] @ [wl;wr] + b)
// Block = 64 dst rows x N=256 full. 256 thr, warp grid 2(m) x 4(n), warp 32x64.
// Phase 1: warps gather 8 rows each into As_agg; cp.async concurrently
//          prefetches FULL root rows (As_root, 2048 float4) and B stages 0/1.
// Phase 2: 16 iters of BK=16 (it<8: As_agg/wl, it>=8: As_root/wr); B 2-stage.
// ---------------------------------------------------------------------------
#define A_ROW 132                 /* floats per A row (smem stride)           */
#define A_SZ  (64 * A_ROW)
#define B_ROW 264
#define B_ST  (16 * B_ROW)
#define SMEM_GEMM1 ((2 * A_SZ + 2 * B_ST) * 4)   /* 101376 B                  */

__global__ void __launch_bounds__(256, 2) k_gemm1(const float* __restrict__ x,
                                                  const float* __restrict__ wl,
                                                  const float* __restrict__ wr,
                                                  const float* __restrict__ bias) {
    extern __shared__ float sm[];
    float* As_agg  = sm;                    // [64][132]
    float* As_root = sm + A_SZ;             // [64][132]
    float* Bbuf    = sm + 2 * A_SZ;         // 2 stages of [16][264]

    const int t = threadIdx.x;
    const int lane = t & 31, warp = t >> 5;
    const int warp_m = warp & 1;            // 0..1
    const int warp_n = warp >> 1;           // 0..3
    const int m0 = blockIdx.x * 64;
    const int fr = lane >> 2;               // 0..7
    const int fc = lane & 3;                // 0..3

    auto issue_B = [&](int it, int st) {
        const int kk = (it & 7) * 16;
        const float* Bbase = (it < 8) ? wl : wr;
        float* Bs = Bbuf + st * B_ST;
        const int nq = (t & 63) * 4;
        #pragma unroll
        for (int i = 0; i < 4; i++) {
            int krow = (t + i * 256) >> 6;  // 0..15
            cp16(s2u(Bs + krow * B_ROW + nq),
                 Bbase + (size_t)(kk + krow) * CHID + nq);
        }
    };

    // ---- prefetch: FULL root rows (64 x 128 floats = 2048 float4) + B 0/1 ----
    {
        #pragma unroll
        for (int i = 0; i < 8; i++) {
            int idx = t + i * 256;          // 0..2047
            int row = idx >> 5;             // 0..63
            int cq  = (idx & 31) * 4;       // 0..124
            cp16(s2u(As_root + row * A_ROW + cq),
                 x + (size_t)(m0 + row) * CIN + cq);
        }
        issue_B(0, 0);
        asm volatile("cp.async.commit_group;");
        issue_B(1, 1);
        asm volatile("cp.async.commit_group;");
    }

    // ---- phase 1: gather-mean, warp handles rows warp*8 .. warp*8+7 ----
    for (int j = 0; j < 8; j++) {
        int r = warp * 8 + j;
        int w = m0 + r;
        int e0 = g_off1[w], e1 = g_off1[w + 1];
        float4 acc = make_float4(0.f, 0.f, 0.f, 0.f);
        int i = e0;
        for (; i + 3 < e1; i += 4) {
            int s0 = g_csr1[i], s1 = g_csr1[i + 1];
            int s2 = g_csr1[i + 2], s3 = g_csr1[i + 3];
            float4 v0 = ((const float4*)(x + (size_t)s0 * CIN))[lane];
            float4 v1 = ((const float4*)(x + (size_t)s1 * CIN))[lane];
            float4 v2 = ((const float4*)(x + (size_t)s2 * CIN))[lane];
            float4 v3 = ((const float4*)(x + (size_t)s3 * CIN))[lane];
            acc.x += v0.x + v1.x + v2.x + v3.x;
            acc.y += v0.y + v1.y + v2.y + v3.y;
            acc.z += v0.z + v1.z + v2.z + v3.z;
            acc.w += v0.w + v1.w + v2.w + v3.w;
        }
        for (; i < e1; i++) {
            float4 v = ((const float4*)(x + (size_t)g_csr1[i] * CIN))[lane];
            acc.x += v.x; acc.y += v.y; acc.z += v.z; acc.w += v.w;
        }
        float id = 1.0f / fmaxf((float)(e1 - e0), 1.0f);
        acc.x *= id; acc.y *= id; acc.z *= id; acc.w *= id;
        *(float4*)(As_agg + r * A_ROW + lane * 4) = acc;
    }

    asm volatile("cp.async.wait_group 0;");
    __syncthreads();

    // ---- phase 2: tf32 mainloop ----
    float acc[2][8][4] = {};
    for (int it = 0; it < 16; ++it) {
        const int buf = it & 1;
        const int kk = (it & 7) * 16;
        const float* A = (it < 8) ? As_agg : As_root;
        const float* B = Bbuf + buf * B_ST;

        #pragma unroll
        for (int ks = 0; ks < 2; ks++) {
            const int kb = ks * 8;
            uint32_t a[2][4], b[8][2];
            #pragma unroll
            for (int mt = 0; mt < 2; mt++) {
                int mr = warp_m * 32 + mt * 16 + fr;
                a[mt][0] = f2tf(A[mr * A_ROW + kk + kb + fc]);
                a[mt][1] = f2tf(A[(mr + 8) * A_ROW + kk + kb + fc]);
                a[mt][2] = f2tf(A[mr * A_ROW + kk + kb + fc + 4]);
                a[mt][3] = f2tf(A[(mr + 8) * A_ROW + kk + kb + fc + 4]);
            }
            #pragma unroll
            for (int nt = 0; nt < 8; nt++) {
                int nc = warp_n * 64 + nt * 8 + fr;
                b[nt][0] = f2tf(B[(kb + fc) * B_ROW + nc]);
                b[nt][1] = f2tf(B[(kb + fc + 4) * B_ROW + nc]);
            }
            #pragma unroll
            for (int mt = 0; mt < 2; mt++)
                #pragma unroll
                for (int nt = 0; nt < 8; nt++)
                    mma_tf32(acc[mt][nt], a[mt], b[nt]);
        }

        __syncthreads();                     // all warps done with buf
        if (it + 2 < 16) {
            issue_B(it + 2, buf);
            asm volatile("cp.async.commit_group;");
        }
        asm volatile("cp.async.wait_group 1;");
        __syncthreads();                     // next buf ready
    }

    // ---- epilogue: bias + relu -> g_h (625*64 == CN1 exact, no bounds) ----
    #pragma unroll
    for (int mt = 0; mt < 2; mt++) {
        int gm = m0 + warp_m * 32 + mt * 16 + fr;
        #pragma unroll
        for (int nt = 0; nt < 8; nt++) {
            int gn = warp_n * 64 + nt * 8 + (fc << 1);
            float b0 = bias[gn], b1 = bias[gn + 1];
            float2 v0 = make_float2(fmaxf(acc[mt][nt][0] + b0, 0.f),
                                    fmaxf(acc[mt][nt][1] + b1, 0.f));
            *(float2*)(g_h + (size_t)gm * CHID + gn) = v0;
            float2 v1 = make_float2(fmaxf(acc[mt][nt][2] + b0, 0.f),
                                    fmaxf(acc[mt][nt][3] + b1, 0.f));
            *(float2*)(g_h + (size_t)(gm + 8) * CHID + gn) = v1;
        }
    }
}

// ---------------------------------------------------------------------------
// FUSED layer-2: gather-mean + GEMM + log_softmax. Warp per dst row.
// ---------------------------------------------------------------------------
__global__ void __launch_bounds__(256) k_gemm2(const float* __restrict__ wl,
                                               const float* __restrict__ wr,
                                               const float* __restrict__ bias,
                                               float* __restrict__ out) {
    __shared__ float As[8][512];
    int warp = threadIdx.x >> 5, lane = threadIdx.x & 31;
    int m = blockIdx.x * 8 + warp;
    if (m >= CN2) return;

    // inline gather-mean of neighbor h rows
    {
        int e0 = g_off2[m], e1 = g_off2[m + 1];
        float4 a0 = make_float4(0.f, 0.f, 0.f, 0.f);
        float4 a1 = a0;
        int i = e0;
        for (; i + 1 < e1; i += 2) {
            const float4* p0 = (const float4*)(g_h + (size_t)g_csr2[i] * CHID);
            const float4* p1 = (const float4*)(g_h + (size_t)g_csr2[i + 1] * CHID);
            float4 u0 = p0[lane], u1 = p0[lane + 32];
            float4 v0 = p1[lane], v1 = p1[lane + 32];
            a0.x += u0.x + v0.x; a0.y += u0.y + v0.y;
            a0.z += u0.z + v0.z; a0.w += u0.w + v0.w;
            a1.x += u1.x + v1.x; a1.y += u1.y + v1.y;
            a1.z += u1.z + v1.z; a1.w += u1.w + v1.w;
        }
        for (; i < e1; i++) {
            const float4* p = (const float4*)(g_h + (size_t)g_csr2[i] * CHID);
            float4 u0 = p[lane], u1 = p[lane + 32];
            a0.x += u0.x; a0.y += u0.y; a0.z += u0.z; a0.w += u0.w;
            a1.x += u1.x; a1.y += u1.y; a1.z += u1.z; a1.w += u1.w;
        }
        float id = 1.0f / fmaxf((float)(e1 - e0), 1.0f);
        a0.x *= id; a0.y *= id; a0.z *= id; a0.w *= id;
        a1.x *= id; a1.y *= id; a1.z *= id; a1.w *= id;
        ((float4*)As[warp])[lane] = a0;
        ((float4*)As[warp])[lane + 32] = a1;
    }
    #pragma unroll
    for (int i = 0; i < 8; i++)
        As[warp][CHID + lane + 32 * i] = g_h[(size_t)m * CHID + lane + 32 * i];
    __syncwarp();

    float acc0 = 0.f, acc1 = 0.f;
    const float* A = As[warp];
    #pragma unroll 8
    for (int k = 0; k < CHID; k++) {
        float a = A[k];
        acc0 += a * wl[k * COUT + lane];
        acc1 += a * wl[k * COUT + lane + 32];
    }
    #pragma unroll 8
    for (int k = 0; k < CHID; k++) {
        float a = A[CHID + k];
        acc0 += a * wr[k * COUT + lane];
        acc1 += a * wr[k * COUT + lane + 32];
    }
    acc0 += bias[lane];
    acc1 += bias[lane + 32];

    float mx = fmaxf(acc0, acc1);
    #pragma unroll
    for (int o = 16; o > 0; o >>= 1) mx = fmaxf(mx, __shfl_xor_sync(0xFFFFFFFFu, mx, o));
    float s = expf(acc0 - mx) + expf(acc1 - mx);
    #pragma unroll
    for (int o = 16; o > 0; o >>= 1) s += __shfl_xor_sync(0xFFFFFFFFu, s, o);
    float lse = mx + logf(s);
    out[(size_t)m * COUT + lane]      = acc0 - lse;
    out[(size_t)m * COUT + lane + 32] = acc1 - lse;
}

// ---------------------------------------------------------------------------
extern "C" void kernel_launch(void* const* d_in, const int* in_sizes, int n_in,
                              void* d_out, int out_size) {
    const float* x    = (const float*)d_in[0];
    const int*   src1 = (const int*)d_in[1];
    const int*   dst1 = (const int*)d_in[2];
    const int*   src2 = (const int*)d_in[3];
    const int*   dst2 = (const int*)d_in[4];
    const float* wl1  = (const float*)d_in[5];
    const float* bl1  = (const float*)d_in[6];
    const float* wr1  = (const float*)d_in[7];
    const float* wl2  = (const float*)d_in[8];
    const float* bl2  = (const float*)d_in[9];
    const float* wr2  = (const float*)d_in[10];
    int E1 = in_sizes[1];
    int E2 = in_sizes[3];

    cudaFuncSetAttribute(k_gemm1, cudaFuncAttributeMaxDynamicSharedMemorySize,
                         SMEM_GEMM1);

    k_zero<<<(CN1 + 1023) / 1024, 1024>>>();
    k_count<<<(E1 + E2 + 255) / 256, 256>>>(dst1, dst2, E1, E2);
    k_scan_a<<<NB1 + NB2, 1024>>>();
    k_scan_c<<<NB1 + NB2, 1024>>>(E1, E2);
    k_fill<<<(E1 + E2 + 255) / 256, 256>>>(src1, dst1, src2, dst2, E1, E2);
    k_gemm1<<<CN1 / 64, 256, SMEM_GEMM1>>>(x, wl1, wr1, bl1);
    k_gemm2<<<(CN2 + 7) / 8, 256>>>(wl2, wr2, bl2, (float*)d_out);
}

// round 11
// speedup vs baseline: 1.2711x; 1.2711x over previous
#include <cuda_runtime.h>
#include <cstdint>

#define CN0  400000
#define CN1  40000
#define CN2  4000
#define CIN  128
#define CHID 256
#define COUT 64
#define CE1  640000
#define CE2  64000
#define NB1  40
#define NB2  4
#define NBT  (NB1 + NB2)

// ---- scratch (device globals: no allocation allowed) ----
__device__ float g_agg1[CN1 * CIN];
__device__ float g_h   [CN1 * CHID];
__device__ int   g_cnt1[CN1];
__device__ int   g_off1[CN1 + 1];
__device__ int   g_csr1[CE1];
__device__ int   g_cnt2[CN2];
__device__ int   g_off2[CN2 + 1];
__device__ int   g_csr2[CE2];
__device__ int   g_bsum[64];
__device__ int   g_scan_done;

// ---------------------------------------------------------------------------
__global__ void k_zero() {
    int i = blockIdx.x * blockDim.x + threadIdx.x;
    if (i < CN1) g_cnt1[i] = 0;
    if (i < CN2) g_cnt2[i] = 0;
    if (i == 0) g_scan_done = 0;
}

__global__ void k_count(const int* __restrict__ d1, const int* __restrict__ d2,
                        int E1, int E2) {
    int i = blockIdx.x * blockDim.x + threadIdx.x;
    if (i < E1) atomicAdd(g_cnt1 + d1[i], 1);
    else {
        int j = i - E1;
        if (j < E2) atomicAdd(g_cnt2 + d2[j], 1);
    }
}

// ---------------------------------------------------------------------------
// Single-kernel segmented scan: phase A (block-local scan + publish bsum),
// device-wide spin barrier (44 blocks, all resident), phase C (apply prefix,
// reset cnt as fill cursor, set off[n]). Blocks 0..39: layer1, 40..43: layer2.
// ---------------------------------------------------------------------------
__global__ void __launch_bounds__(1024) k_scan(int E1, int E2) {
    int b = blockIdx.x;
    int lay = (b >= NB1);
    int bb = lay ? b - NB1 : b;
    int n = lay ? CN2 : CN1;
    int segbase = lay ? NB1 : 0;
    int* cnt = lay ? g_cnt2 : g_cnt1;
    int* off = lay ? g_off2 : g_off1;
    __shared__ int ps[1024];
    __shared__ int add_s;
    int t = threadIdx.x;
    int i = bb * 1024 + t;
    int v = (i < n) ? cnt[i] : 0;
    ps[t] = v;
    __syncthreads();
    #pragma unroll
    for (int d = 1; d < 1024; d <<= 1) {
        int u = (t >= d) ? ps[t - d] : 0;
        __syncthreads();
        ps[t] += u;
        __syncthreads();
    }
    int local_ex = ps[t] - v;
    if (t == 0) g_bsum[b] = ps[1023];
    __threadfence();
    __syncthreads();
    // device-wide barrier: all 44 blocks resident (<=148 SMs) -> spin is safe
    if (t == 0) {
        atomicAdd(&g_scan_done, 1);
        while (*(volatile int*)&g_scan_done < NBT) { }
        __threadfence();
        int s = 0;
        for (int j = segbase; j < b; j++) s += g_bsum[j];
        add_s = s;
    }
    __syncthreads();
    int add = add_s;
    if (i < n) { off[i] = local_ex + add; cnt[i] = 0; }
    if (i == 0) off[n] = lay ? E2 : E1;
}

__global__ void k_fill(const int* __restrict__ s1, const int* __restrict__ d1,
                       const int* __restrict__ s2, const int* __restrict__ d2,
                       int E1, int E2) {
    int i = blockIdx.x * blockDim.x + threadIdx.x;
    if (i < E1) {
        int d = d1[i];
        int pos = atomicAdd(g_cnt1 + d, 1);
        g_csr1[g_off1[d] + pos] = s1[i];
    } else {
        int j = i - E1;
        if (j < E2) {
            int d = d2[j];
            int pos = atomicAdd(g_cnt2 + d, 1);
            g_csr2[g_off2[d] + pos] = s2[j];
        }
    }
}

// ---------------------------------------------------------------------------
// layer-1 gather-mean: warp per dst row, 128 floats = 32 lanes x float4
// ---------------------------------------------------------------------------
__global__ void __launch_bounds__(256) k_gather1(const float* __restrict__ x) {
    int w = (blockIdx.x * blockDim.x + threadIdx.x) >> 5;
    if (w >= CN1) return;
    int lane = threadIdx.x & 31;
    int e0 = g_off1[w], e1 = g_off1[w + 1];
    float4 acc = make_float4(0.f, 0.f, 0.f, 0.f);
    int i = e0;
    for (; i + 3 < e1; i += 4) {
        int s0 = g_csr1[i], s1 = g_csr1[i + 1], s2 = g_csr1[i + 2], s3 = g_csr1[i + 3];
        float4 v0 = ((const float4*)(x + (size_t)s0 * CIN))[lane];
        float4 v1 = ((const float4*)(x + (size_t)s1 * CIN))[lane];
        float4 v2 = ((const float4*)(x + (size_t)s2 * CIN))[lane];
        float4 v3 = ((const float4*)(x + (size_t)s3 * CIN))[lane];
        acc.x += v0.x + v1.x + v2.x + v3.x;
        acc.y += v0.y + v1.y + v2.y + v3.y;
        acc.z += v0.z + v1.z + v2.z + v3.z;
        acc.w += v0.w + v1.w + v2.w + v3.w;
    }
    for (; i < e1; i++) {
        int s = g_csr1[i];
        float4 v = ((const float4*)(x + (size_t)s * CIN))[lane];
        acc.x += v.x; acc.y += v.y; acc.z += v.z; acc.w += v.w;
    }
    float id = 1.0f / fmaxf((float)(e1 - e0), 1.0f);
    acc.x *= id; acc.y *= id; acc.z *= id; acc.w *= id;
    ((float4*)(g_agg1 + (size_t)w * CIN))[lane] = acc;
}

// ---------------------------------------------------------------------------
// tf32 helpers — NOTE: raw fp32 bits fed to mma.tf32 (HW truncates to tf32);
// removes 48 CVT per warp-iteration from the mainloop issue stream.
// ---------------------------------------------------------------------------
__device__ __forceinline__ void mma_tf32(float* c, const uint32_t* a, const uint32_t* b) {
    asm volatile(
        "mma.sync.aligned.m16n8k8.row.col.f32.tf32.tf32.f32 "
        "{%0,%1,%2,%3}, {%4,%5,%6,%7}, {%8,%9}, {%0,%1,%2,%3};"
        : "+f"(c[0]), "+f"(c[1]), "+f"(c[2]), "+f"(c[3])
        : "r"(a[0]), "r"(a[1]), "r"(a[2]), "r"(a[3]), "r"(b[0]), "r"(b[1]));
}

__device__ __forceinline__ uint32_t s2u(const void* p) {
    return (uint32_t)__cvta_generic_to_shared(p);
}

__device__ __forceinline__ void cp16(uint32_t dst, const void* src) {
    asm volatile("cp.async.cg.shared.global [%0], [%1], 16;"
                 :: "r"(dst), "l"(src));
}

// ---------------------------------------------------------------------------
// layer-1 GEMM (tf32, 3-stage cp.async pipeline, BM=64 x BN=256):
//   h = relu([agg1 | x_root] @ [w_l1;w_r1] + b_l1)
// M=40000 (625 blocks x 64 rows, exact), K=256 (16 iters BK=16), N=256 full.
// 256 thr, warp grid 2(m) x 4(n), warp tile 32x64.
// ---------------------------------------------------------------------------
#define A_ST 1280    /* 64*20 floats per stage */
#define B_ST 4224    /* 16*264 floats per stage */
#define SMEM_GEMM1 ((3 * (A_ST + B_ST)) * 4)

__global__ void __launch_bounds__(256, 2) k_gemm1(const float* __restrict__ x,
                                                  const float* __restrict__ wl,
                                                  const float* __restrict__ wr,
                                                  const float* __restrict__ bias) {
    extern __shared__ float sm[];
    float* Abuf = sm;                  // 3 stages of [64][20]
    float* Bbuf = sm + 3 * A_ST;       // 3 stages of [16][264]

    const int t = threadIdx.x;
    const int lane = t & 31, warp = t >> 5;
    const int warp_m = warp & 1;       // 0..1 -> 32-row slab
    const int warp_n = warp >> 1;      // 0..3 -> 64-col slab
    const int m0 = blockIdx.x * 64;
    const int fr = lane >> 2;          // 0..7
    const int fc = lane & 3;           // 0..3

    const int a_row = t >> 2,  a_kq = (t & 3) * 4;
    const int b_nq  = (t & 63) * 4;

    float acc[2][8][4] = {};

    auto issue = [&](int it, int st) {
        const int kk = (it & 7) * 16;
        const float* Abase = (it < 8) ? g_agg1 : x;
        const float* Bbase = (it < 8) ? wl : wr;
        float* As = Abuf + st * A_ST;
        float* Bs = Bbuf + st * B_ST;
        cp16(s2u(As + a_row * 20 + a_kq),
             Abase + (size_t)(m0 + a_row) * CIN + kk + a_kq);
        #pragma unroll
        for (int i = 0; i < 4; i++) {
            int krow = (t + i * 256) >> 6;      // 0..15
            cp16(s2u(Bs + krow * 264 + b_nq),
                 Bbase + (size_t)(kk + krow) * CHID + b_nq);
        }
    };

    issue(0, 0);
    asm volatile("cp.async.commit_group;");
    issue(1, 1);
    asm volatile("cp.async.commit_group;");

    int st = 0;
    for (int it = 0; it < 16; ++it) {
        asm volatile("cp.async.wait_group 1;");
        __syncthreads();
        if (it + 2 < 16) issue(it + 2, (st + 2) % 3);
        asm volatile("cp.async.commit_group;");

        const uint32_t* A = (const uint32_t*)(Abuf + st * A_ST);
        const uint32_t* B = (const uint32_t*)(Bbuf + st * B_ST);
        #pragma unroll
        for (int ks = 0; ks < 2; ks++) {
            const int kb = ks * 8;
            uint32_t a[2][4], b[8][2];
            #pragma unroll
            for (int mt = 0; mt < 2; mt++) {
                int mr = warp_m * 32 + mt * 16 + fr;
                a[mt][0] = A[mr * 20 + kb + fc];
                a[mt][1] = A[(mr + 8) * 20 + kb + fc];
                a[mt][2] = A[mr * 20 + kb + fc + 4];
                a[mt][3] = A[(mr + 8) * 20 + kb + fc + 4];
            }
            #pragma unroll
            for (int nt = 0; nt < 8; nt++) {
                int nc = warp_n * 64 + nt * 8 + fr;
                b[nt][0] = B[(kb + fc) * 264 + nc];
                b[nt][1] = B[(kb + fc + 4) * 264 + nc];
            }
            #pragma unroll
            for (int mt = 0; mt < 2; mt++)
                #pragma unroll
                for (int nt = 0; nt < 8; nt++)
                    mma_tf32(acc[mt][nt], a[mt], b[nt]);
        }
        st = (st + 1) % 3;
    }

    // ---- epilogue: bias + relu, write g_h (625*64 == CN1 exact) ----
    #pragma unroll
    for (int mt = 0; mt < 2; mt++) {
        int gm = m0 + warp_m * 32 + mt * 16 + fr;
        #pragma unroll
        for (int nt = 0; nt < 8; nt++) {
            int gn = warp_n * 64 + nt * 8 + (fc << 1);
            float b0 = bias[gn], b1 = bias[gn + 1];
            float2 v0 = make_float2(fmaxf(acc[mt][nt][0] + b0, 0.f),
                                    fmaxf(acc[mt][nt][1] + b1, 0.f));
            *(float2*)(g_h + (size_t)gm * CHID + gn) = v0;
            float2 v1 = make_float2(fmaxf(acc[mt][nt][2] + b0, 0.f),
                                    fmaxf(acc[mt][nt][3] + b1, 0.f));
            *(float2*)(g_h + (size_t)(gm + 8) * CHID + gn) = v1;
        }
    }
}

// ---------------------------------------------------------------------------
// FUSED layer-2: gather-mean + GEMM + log_softmax. Warp per dst row.
// ---------------------------------------------------------------------------
__global__ void __launch_bounds__(256) k_gemm2(const float* __restrict__ wl,
                                               const float* __restrict__ wr,
                                               const float* __restrict__ bias,
                                               float* __restrict__ out) {
    __shared__ float As[8][512];
    int warp = threadIdx.x >> 5, lane = threadIdx.x & 31;
    int m = blockIdx.x * 8 + warp;
    if (m >= CN2) return;

    // inline gather-mean of neighbor h rows
    {
        int e0 = g_off2[m], e1 = g_off2[m + 1];
        float4 a0 = make_float4(0.f, 0.f, 0.f, 0.f);
        float4 a1 = a0;
        int i = e0;
        for (; i + 1 < e1; i += 2) {
            const float4* p0 = (const float4*)(g_h + (size_t)g_csr2[i] * CHID);
            const float4* p1 = (const float4*)(g_h + (size_t)g_csr2[i + 1] * CHID);
            float4 u0 = p0[lane], u1 = p0[lane + 32];
            float4 v0 = p1[lane], v1 = p1[lane + 32];
            a0.x += u0.x + v0.x; a0.y += u0.y + v0.y;
            a0.z += u0.z + v0.z; a0.w += u0.w + v0.w;
            a1.x += u1.x + v1.x; a1.y += u1.y + v1.y;
            a1.z += u1.z + v1.z; a1.w += u1.w + v1.w;
        }
        for (; i < e1; i++) {
            const float4* p = (const float4*)(g_h + (size_t)g_csr2[i] * CHID);
            float4 u0 = p[lane], u1 = p[lane + 32];
            a0.x += u0.x; a0.y += u0.y; a0.z += u0.z; a0.w += u0.w;
            a1.x += u1.x; a1.y += u1.y; a1.z += u1.z; a1.w += u1.w;
        }
        float id = 1.0f / fmaxf((float)(e1 - e0), 1.0f);
        a0.x *= id; a0.y *= id; a0.z *= id; a0.w *= id;
        a1.x *= id; a1.y *= id; a1.z *= id; a1.w *= id;
        ((float4*)As[warp])[lane] = a0;
        ((float4*)As[warp])[lane + 32] = a1;
    }
    #pragma unroll
    for (int i = 0; i < 8; i++)
        As[warp][CHID + lane + 32 * i] = g_h[(size_t)m * CHID + lane + 32 * i];
    __syncwarp();

    float acc0 = 0.f, acc1 = 0.f;
    const float* A = As[warp];
    #pragma unroll 8
    for (int k = 0; k < CHID; k++) {
        float a = A[k];
        acc0 += a * wl[k * COUT + lane];
        acc1 += a * wl[k * COUT + lane + 32];
    }
    #pragma unroll 8
    for (int k = 0; k < CHID; k++) {
        float a = A[CHID + k];
        acc0 += a * wr[k * COUT + lane];
        acc1 += a * wr[k * COUT + lane + 32];
    }
    acc0 += bias[lane];
    acc1 += bias[lane + 32];

    float mx = fmaxf(acc0, acc1);
    #pragma unroll
    for (int o = 16; o > 0; o >>= 1) mx = fmaxf(mx, __shfl_xor_sync(0xFFFFFFFFu, mx, o));
    float s = expf(acc0 - mx) + expf(acc1 - mx);
    #pragma unroll
    for (int o = 16; o > 0; o >>= 1) s += __shfl_xor_sync(0xFFFFFFFFu, s, o);
    float lse = mx + logf(s);
    out[(size_t)m * COUT + lane]      = acc0 - lse;
    out[(size_t)m * COUT + lane + 32] = acc1 - lse;
}

// ---------------------------------------------------------------------------
extern "C" void kernel_launch(void* const* d_in, const int* in_sizes, int n_in,
                              void* d_out, int out_size) {
    const float* x    = (const float*)d_in[0];
    const int*   src1 = (const int*)d_in[1];
    const int*   dst1 = (const int*)d_in[2];
    const int*   src2 = (const int*)d_in[3];
    const int*   dst2 = (const int*)d_in[4];
    const float* wl1  = (const float*)d_in[5];
    const float* bl1  = (const float*)d_in[6];
    const float* wr1  = (const float*)d_in[7];
    const float* wl2  = (const float*)d_in[8];
    const float* bl2  = (const float*)d_in[9];
    const float* wr2  = (const float*)d_in[10];
    int E1 = in_sizes[1];
    int E2 = in_sizes[3];

    cudaFuncSetAttribute(k_gemm1, cudaFuncAttributeMaxDynamicSharedMemorySize,
                         SMEM_GEMM1);

    k_zero<<<(CN1 + 1023) / 1024, 1024>>>();
    k_count<<<(E1 + E2 + 255) / 256, 256>>>(dst1, dst2, E1, E2);
    k_scan<<<NBT, 1024>>>(E1, E2);
    k_fill<<<(E1 + E2 + 255) / 256, 256>>>(src1, dst1, src2, dst2, E1, E2);
    k_gather1<<<(CN1 * 32 + 255) / 256, 256>>>(x);
    k_gemm1<<<CN1 / 64, 256, SMEM_GEMM1>>>(x, wl1, wr1, bl1);
    k_gemm2<<<(CN2 + 7) / 8, 256>>>(wl2, wr2, bl2, (float*)d_out);
}